// round 11
// baseline (speedup 1.0000x reference)
#include <cuda_runtime.h>
#include <cstdint>

#define NEGF   (-1e30f)
#define EPSF   (1e-7f)
#define LN2F   (0.6931471805599453f)
#define KB     8            // time steps per ring block
#define RINGT  16           // ring time slots (2 blocks)
#define NPROD  160          // producer threads (5 warps)
#define NTHR   192
#define NS     5            // states per DP lane (32*5 = 160 >= 129)
#define NCLS   65           // L labels + blank
#define SLOTW  66
#define MAXQ   4

__device__ __forceinline__ float ex2f_(float x) {
    float r; asm("ex2.approx.ftz.f32 %0, %1;" : "=f"(r) : "f"(x)); return r;
}
__device__ __forceinline__ float lg2f_(float x) {
    float r; asm("lg2.approx.ftz.f32 %0, %1;" : "=f"(r) : "f"(x)); return r;
}
__device__ __forceinline__ uint32_t s2u32(const void* p) {
    uint32_t a;
    asm("{ .reg .u64 t; cvta.to.shared.u64 t, %1; cvt.u32.u64 %0, t; }" : "=r"(a) : "l"(p));
    return a;
}
__device__ __forceinline__ void mbar_init(uint32_t m, uint32_t cnt) {
    asm volatile("mbarrier.init.shared.b64 [%0], %1;" :: "r"(m), "r"(cnt) : "memory");
}
__device__ __forceinline__ void mbar_arrive(uint32_t m) {
    asm volatile("mbarrier.arrive.shared.b64 _, [%0];" :: "r"(m) : "memory");
}
__device__ __forceinline__ void mbar_wait_acq(uint32_t m, uint32_t parity) {
    asm volatile(
        "{\n\t.reg .pred P;\n"
        "W%=:\n\t"
        "mbarrier.try_wait.parity.acquire.cta.shared::cta.b64 P, [%0], %1, 0x989680;\n\t"
        "@P bra D%=;\n\t"
        "bra W%=;\n"
        "D%=:\n\t}"
        :: "r"(m), "r"(parity) : "memory");
}

// One CTA per batch row. 5 producer warps gather the 65 unique class probs
// per time step, compute log2(p+eps), fill a 16-slot shared ring (4-phase
// register pipeline = 16 outstanding LDGs/thread). The DP runs on ONE warp
// in log2 space: lane l holds states [5l,5l+5) in registers, neighbors via
// two __shfl_up, zero barriers on the recurrence. The DP warp's index is a
// per-block hash so co-resident CTAs place their MUFU-heavy DP warps on
// DIFFERENT SM sub-partitions (SMSP = warp_id % 4), halving MUFU contention.
__global__ __launch_bounds__(NTHR)
void CTCLayer_5669356831169_kernel(const int* __restrict__ y_true,
                                   const float* __restrict__ y_pred,
                                   float* __restrict__ out,
                                   int T, int C, int L)
{
    __shared__ int   classes[NCLS];
    __shared__ float ring[RINGT * SLOTW];
    __shared__ float afinal[32 * NS];
    __shared__ __align__(8) unsigned long long mbars[4]; // full[0,1], empty[2,3]
    __shared__ int sh_ll;

    const int b     = blockIdx.x;
    const int tid   = threadIdx.x;
    const int blank = C - 1;
    const int S     = 2 * L + 1;

    // DP warp index: spread across SMSPs between co-resident CTAs.
    const int dpw  = ((b >> 2) + b) & 3;
    const int pw   = tid >> 5;          // warp index 0..5
    const int lane = tid & 31;

    const uint32_t mb = s2u32(mbars);
    #define FULLB(r)  (mb + (uint32_t)(r) * 8u)
    #define EMPTYB(r) (mb + (uint32_t)(2 + (r)) * 8u)

    const int* yt = y_true + (size_t)b * L;

    for (int j = tid; j < NCLS; j += NTHR) {
        int c = blank;
        if (j < L) { int raw = yt[j]; c = (raw < 0) ? blank : raw; }
        classes[j] = c;
    }
    if (tid == 0) {
        int ll = 0;
        for (int i = 0; i < L; ++i) ll += (yt[i] != -1);
        sh_ll = ll;
        for (int r = 0; r < 2; ++r) {
            mbar_init(FULLB(r), NPROD);
            mbar_init(EMPTYB(r), 1);
        }
    }
    __syncthreads();
    const int ll = sh_ll;

    const int NB = (T + KB - 1) / KB;          // 64

    if (pw != dpw) {
        // ------------------------ producers (4-phase) ------------------------
        const int pid = (pw < dpw ? pw : pw - 1) * 32 + lane;   // 0..159
        const float* yrow = y_pred + (size_t)b * T * C;
        const int LPB = KB * NCLS;              // 520 gathers per block

        int  uu[MAXQ], jj[MAXQ], cc[MAXQ];
        bool ok[MAXQ];
        #pragma unroll
        for (int i = 0; i < MAXQ; ++i) {
            int q = pid + NPROD * i;
            ok[i] = (q < LPB);
            int u = ok[i] ? q / NCLS : 0;
            int j = ok[i] ? q % NCLS : 0;
            uu[i] = u; jj[i] = j; cc[i] = classes[j];
        }

        float bv0[MAXQ], bv1[MAXQ], bv2[MAXQ], bv3[MAXQ];

        #define PLDG(buf, m) do {                                             \
            if ((m) < NB) {                                                   \
                int _t0 = (m) * KB;                                           \
                _Pragma("unroll")                                             \
                for (int i = 0; i < MAXQ; ++i) {                              \
                    int _t = _t0 + uu[i];                                     \
                    buf[i] = (ok[i] && _t < T)                                \
                        ? __ldcs(yrow + (size_t)_t * C + cc[i]) : 1.0f;       \
                } } } while (0)

        #define PBLK(m, buf) do {                                             \
            if ((m) < NB) {                                                   \
                if ((m) >= 2)                                                 \
                    mbar_wait_acq(EMPTYB((m) & 1), (((m) >> 1) - 1) & 1);     \
                int _t0 = (m) * KB;                                           \
                _Pragma("unroll")                                             \
                for (int i = 0; i < MAXQ; ++i) {                              \
                    int _t = _t0 + uu[i];                                     \
                    if (ok[i] && _t < T)                                      \
                        ring[(_t & (RINGT - 1)) * SLOTW + jj[i]]              \
                            = lg2f_(buf[i] + EPSF);                           \
                }                                                             \
                mbar_arrive(FULLB((m) & 1));                                  \
            } } while (0)

        PLDG(bv0, 0); PLDG(bv1, 1); PLDG(bv2, 2); PLDG(bv3, 3);

        for (int k = 0; k < NB; k += 4) {
            PBLK(k,     bv0);  PLDG(bv0, k + 4);
            PBLK(k + 1, bv1);  PLDG(bv1, k + 5);
            PBLK(k + 2, bv2);  PLDG(bv2, k + 6);
            PBLK(k + 3, bv3);  PLDG(bv3, k + 7);
        }
        #undef PBLK
        #undef PLDG
    } else {
        // ------------------------ DP warp (log2 space) ------------------------
        const int l = lane;
        int  col[NS];
        bool allow2[NS], validb[NS], lead[NS];
        #pragma unroll
        for (int j = 0; j < NS; ++j) {
            int s = NS * l + j;
            bool sv = (s < S) && (s < 2 * ll + 1);
            validb[j] = sv;
            lead[j]   = sv && (s < 2);
            allow2[j] = false;
            col[j]    = NCLS - 1;                // blank column default
            if ((s & 1) && s < S) {
                int i = (s - 1) >> 1;            // 0..63
                col[j] = i;
                if (i >= 1) {
                    int c1 = classes[i], c2 = classes[i - 1];
                    allow2[j] = (c1 != blank) && (c1 != c2);
                }
            }
        }

        float a[NS];
        #pragma unroll
        for (int j = 0; j < NS; ++j) a[j] = NEGF;

        for (int blk = 0; blk < NB; ++blk) {
            int slot = blk & 1;
            mbar_wait_acq(FULLB(slot), (blk >> 1) & 1);
            const float* bp = ring + (size_t)(slot * KB * SLOTW);

            #pragma unroll
            for (int u = 0; u < KB; ++u) {
                int t = blk * KB + u;
                if (t < T) {
                    const float* rp = bp + u * SLOTW;
                    float le[NS];
                    #pragma unroll
                    for (int j = 0; j < NS; ++j) le[j] = rp[col[j]];

                    float up1 = __shfl_up_sync(0xffffffffu, a[NS - 1], 1);
                    float up2 = __shfl_up_sync(0xffffffffu, a[NS - 2], 1);
                    if (l == 0) { up1 = NEGF; up2 = NEGF; }

                    float na[NS];
                    #pragma unroll
                    for (int j = 0; j < NS; ++j) {
                        float bb = (j >= 1) ? a[j - 1] : up1;
                        float cc = (j >= 2) ? a[j - 2] : ((j == 1) ? up1 : up2);
                        cc = allow2[j] ? cc : NEGF;
                        float x   = fmaxf(a[j], bb);
                        float n   = fminf(a[j], bb);
                        float hi  = fmaxf(x, cc);
                        float lo  = fminf(n, cc);
                        float mid = fmaxf(n, fminf(x, cc));
                        float sum = 1.0f + ex2f_(lo - hi) + ex2f_(mid - hi);
                        na[j] = validb[j] ? (le[j] + hi + lg2f_(sum)) : NEGF;
                    }
                    if (t == 0) {
                        #pragma unroll
                        for (int j = 0; j < NS; ++j)
                            na[j] = lead[j] ? le[j] : NEGF;
                    }
                    #pragma unroll
                    for (int j = 0; j < NS; ++j) a[j] = na[j];
                }
            }
            __syncwarp();
            if (l == 0) mbar_arrive(EMPTYB(slot));
        }

        #pragma unroll
        for (int j = 0; j < NS; ++j) afinal[NS * l + j] = a[j];
        __syncwarp();
        if (l == 0) {
            float x1 = afinal[2 * ll];
            float x0 = (ll > 0) ? afinal[2 * ll - 1] : NEGF;
            float m  = fmaxf(x1, x0);
            float r  = m + lg2f_(ex2f_(x1 - m) + ex2f_(x0 - m));
            out[b] = -LN2F * r;
        }
    }
    #undef FULLB
    #undef EMPTYB
}

extern "C" void kernel_launch(void* const* d_in, const int* in_sizes, int n_in,
                              void* d_out, int out_size) {
    const int*   y_true = (const int*)d_in[0];
    const float* y_pred = (const float*)d_in[1];
    float*       out    = (float*)d_out;

    const int B = out_size;                 // [B, 1]
    const int L = in_sizes[0] / B;          // 64  (NCLS = L+1 = 65)
    const int C = 1024;
    const int T = in_sizes[1] / (B * C);    // 512

    CTCLayer_5669356831169_kernel<<<B, NTHR>>>(y_true, y_pred, out, T, C, L);
}

// round 13
// speedup vs baseline: 1.0202x; 1.0202x over previous
#include <cuda_runtime.h>
#include <cstdint>

#define NEGF   (-1e30f)
#define EPSF   (1e-7f)
#define LN2F   (0.6931471805599453f)
#define KB     8            // time steps per ring block
#define NRB    4            // ring blocks (deepened from 2)
#define RINGT  (NRB * KB)   // 32 time slots
#define NTDP   32           // DP warp
#define NPROD  160          // producer threads
#define NTHR   192
#define NS     5            // states per DP lane (32*5 = 160 >= 129)
#define NCLS   65           // L labels + blank
#define SLOTW  66
#define MAXQ   4

__device__ __forceinline__ float ex2f_(float x) {
    float r; asm("ex2.approx.ftz.f32 %0, %1;" : "=f"(r) : "f"(x)); return r;
}
__device__ __forceinline__ float lg2f_(float x) {
    float r; asm("lg2.approx.ftz.f32 %0, %1;" : "=f"(r) : "f"(x)); return r;
}
__device__ __forceinline__ uint32_t s2u32(const void* p) {
    uint32_t a;
    asm("{ .reg .u64 t; cvta.to.shared.u64 t, %1; cvt.u32.u64 %0, t; }" : "=r"(a) : "l"(p));
    return a;
}
__device__ __forceinline__ void mbar_init(uint32_t m, uint32_t cnt) {
    asm volatile("mbarrier.init.shared.b64 [%0], %1;" :: "r"(m), "r"(cnt) : "memory");
}
__device__ __forceinline__ void mbar_arrive(uint32_t m) {
    asm volatile("mbarrier.arrive.shared.b64 _, [%0];" :: "r"(m) : "memory");
}
__device__ __forceinline__ void mbar_wait_acq(uint32_t m, uint32_t parity) {
    asm volatile(
        "{\n\t.reg .pred P;\n"
        "W%=:\n\t"
        "mbarrier.try_wait.parity.acquire.cta.shared::cta.b64 P, [%0], %1, 0x989680;\n\t"
        "@P bra D%=;\n\t"
        "bra W%=;\n"
        "D%=:\n\t}"
        :: "r"(m), "r"(parity) : "memory");
}

// One CTA per batch row. 160 producer threads (warps 1-5) gather the 65
// unique class probs per time step, compute log2(p+eps), and fill a 32-slot
// (4-block) shared ring with a 3-phase register pipeline (12 outstanding
// LDGs/thread). The DP runs on ONE warp (warp 0) in log2 space: lane l holds
// states [5l,5l+5) in registers; cross-lane alpha[s-1], alpha[s-2] via two
// __shfl_up per step; zero barriers on the recurrence. Handoff: per-block
// full/empty mbarriers (full count = 160 producer arrives, empty count = 1).
__global__ __launch_bounds__(NTHR)
void CTCLayer_5669356831169_kernel(const int* __restrict__ y_true,
                                   const float* __restrict__ y_pred,
                                   float* __restrict__ out,
                                   int T, int C, int L)
{
    __shared__ int   classes[NCLS];
    __shared__ float ring[RINGT * SLOTW];
    __shared__ float afinal[NTDP * NS];
    __shared__ __align__(8) unsigned long long mbars[2 * NRB]; // full[0..3], empty[4..7]
    __shared__ int sh_ll;

    const int b     = blockIdx.x;
    const int tid   = threadIdx.x;
    const int blank = C - 1;
    const int S     = 2 * L + 1;

    const uint32_t mb = s2u32(mbars);
    #define FULLB(r)  (mb + (uint32_t)(r) * 8u)
    #define EMPTYB(r) (mb + (uint32_t)(NRB + (r)) * 8u)

    const int* yt = y_true + (size_t)b * L;

    for (int j = tid; j < NCLS; j += NTHR) {
        int c = blank;
        if (j < L) { int raw = yt[j]; c = (raw < 0) ? blank : raw; }
        classes[j] = c;
    }
    if (tid == 0) {
        int ll = 0;
        for (int i = 0; i < L; ++i) ll += (yt[i] != -1);
        sh_ll = ll;
        for (int r = 0; r < NRB; ++r) {
            mbar_init(FULLB(r), NPROD);
            mbar_init(EMPTYB(r), 1);
        }
    }
    __syncthreads();
    const int ll = sh_ll;

    const int NB  = (T + KB - 1) / KB;          // 64
    const int NB3 = ((NB + 2) / 3) * 3;         // 66

    if (tid >= NTDP) {
        // ------------------------ producers (3-phase) ------------------------
        const int pid = tid - NTDP;
        const float* yrow = y_pred + (size_t)b * T * C;
        const int LPB = KB * NCLS;              // 520 gathers per block

        int  uu[MAXQ], jj[MAXQ], cc[MAXQ];
        bool ok[MAXQ];
        #pragma unroll
        for (int i = 0; i < MAXQ; ++i) {
            int q = pid + NPROD * i;
            ok[i] = (q < LPB);
            int u = ok[i] ? q / NCLS : 0;
            int j = ok[i] ? q % NCLS : 0;
            uu[i] = u; jj[i] = j; cc[i] = classes[j];
        }

        float bv0[MAXQ], bv1[MAXQ], bv2[MAXQ];

        #define PLDG(buf, m) do {                                             \
            int _t0 = (m) * KB;                                               \
            _Pragma("unroll")                                                 \
            for (int i = 0; i < MAXQ; ++i) {                                  \
                int _t = _t0 + uu[i];                                         \
                buf[i] = (ok[i] && _t < T)                                    \
                    ? __ldcs(yrow + (size_t)_t * C + cc[i]) : 1.0f;           \
            } } while (0)

        #define PSTS(buf, m) do {                                             \
            int _t0 = (m) * KB;                                               \
            _Pragma("unroll")                                                 \
            for (int i = 0; i < MAXQ; ++i) {                                  \
                int _t = _t0 + uu[i];                                         \
                if (ok[i] && _t < T)                                          \
                    ring[(_t & (RINGT - 1)) * SLOTW + jj[i]]                  \
                        = lg2f_(buf[i] + EPSF);                               \
            } } while (0)

        #define PBLK(m, buf) do {                                             \
            if ((m) < NB) {                                                   \
                if ((m) >= NRB)                                               \
                    mbar_wait_acq(EMPTYB((m) & (NRB - 1)),                    \
                                  (((m) / NRB) - 1) & 1);                     \
                PSTS(buf, m);                                                 \
                mbar_arrive(FULLB((m) & (NRB - 1)));                          \
            } } while (0)

        PLDG(bv0, 0); PLDG(bv1, 1); PLDG(bv2, 2);

        for (int k = 0; k < NB3; k += 3) {
            PBLK(k,     bv0);  PLDG(bv0, k + 3);
            PBLK(k + 1, bv1);  PLDG(bv1, k + 4);
            PBLK(k + 2, bv2);  PLDG(bv2, k + 5);
        }
        #undef PBLK
        #undef PSTS
        #undef PLDG
    } else {
        // ------------------------ DP warp (log2 space) ------------------------
        const int l = tid;                       // lane 0..31
        int  col[NS];
        bool allow2[NS], validb[NS], lead[NS];
        #pragma unroll
        for (int j = 0; j < NS; ++j) {
            int s = NS * l + j;
            bool sv = (s < S) && (s < 2 * ll + 1);
            validb[j] = sv;
            lead[j]   = sv && (s < 2);
            allow2[j] = false;
            col[j]    = NCLS - 1;                // blank column default
            if ((s & 1) && s < S) {
                int i = (s - 1) >> 1;            // 0..63
                col[j] = i;
                if (i >= 1) {
                    int c1 = classes[i], c2 = classes[i - 1];
                    allow2[j] = (c1 != blank) && (c1 != c2);
                }
            }
        }

        float a[NS];
        #pragma unroll
        for (int j = 0; j < NS; ++j) a[j] = NEGF;

        for (int blk = 0; blk < NB; ++blk) {
            int slot = blk & (NRB - 1);
            mbar_wait_acq(FULLB(slot), (blk / NRB) & 1);
            const float* bp = ring + (size_t)(slot * KB * SLOTW);

            #pragma unroll
            for (int u = 0; u < KB; ++u) {
                int t = blk * KB + u;
                if (t < T) {
                    const float* rp = bp + u * SLOTW;
                    float le[NS];
                    #pragma unroll
                    for (int j = 0; j < NS; ++j) le[j] = rp[col[j]];

                    float up1 = __shfl_up_sync(0xffffffffu, a[NS - 1], 1);
                    float up2 = __shfl_up_sync(0xffffffffu, a[NS - 2], 1);
                    if (l == 0) { up1 = NEGF; up2 = NEGF; }

                    float na[NS];
                    #pragma unroll
                    for (int j = 0; j < NS; ++j) {
                        float bb = (j >= 1) ? a[j - 1] : up1;
                        float cc = (j >= 2) ? a[j - 2] : ((j == 1) ? up1 : up2);
                        cc = allow2[j] ? cc : NEGF;
                        float x   = fmaxf(a[j], bb);
                        float n   = fminf(a[j], bb);
                        float hi  = fmaxf(x, cc);
                        float lo  = fminf(n, cc);
                        float mid = fmaxf(n, fminf(x, cc));
                        float sum = 1.0f + ex2f_(lo - hi) + ex2f_(mid - hi);
                        na[j] = validb[j] ? (le[j] + hi + lg2f_(sum)) : NEGF;
                    }
                    if (t == 0) {
                        #pragma unroll
                        for (int j = 0; j < NS; ++j)
                            na[j] = lead[j] ? le[j] : NEGF;
                    }
                    #pragma unroll
                    for (int j = 0; j < NS; ++j) a[j] = na[j];
                }
            }
            __syncwarp();
            if (l == 0) mbar_arrive(EMPTYB(slot));
        }

        #pragma unroll
        for (int j = 0; j < NS; ++j) afinal[NS * l + j] = a[j];
        __syncwarp();
        if (l == 0) {
            float x1 = afinal[2 * ll];
            float x0 = (ll > 0) ? afinal[2 * ll - 1] : NEGF;
            float m  = fmaxf(x1, x0);
            float r  = m + lg2f_(ex2f_(x1 - m) + ex2f_(x0 - m));
            out[b] = -LN2F * r;
        }
    }
    #undef FULLB
    #undef EMPTYB
}

extern "C" void kernel_launch(void* const* d_in, const int* in_sizes, int n_in,
                              void* d_out, int out_size) {
    const int*   y_true = (const int*)d_in[0];
    const float* y_pred = (const float*)d_in[1];
    float*       out    = (float*)d_out;

    const int B = out_size;                 // [B, 1]
    const int L = in_sizes[0] / B;          // 64  (NCLS = L+1 = 65)
    const int C = 1024;
    const int T = in_sizes[1] / (B * C);    // 512

    CTCLayer_5669356831169_kernel<<<B, NTHR>>>(y_true, y_pred, out, T, C, L);
}